// round 14
// baseline (speedup 1.0000x reference)
#include <cuda_runtime.h>
#include <math.h>

// Problem constants
#define Bb   2
#define Nn   2048
#define Din  1024
#define Dout 1024
#define Hh   16
#define HDd  64

// Scratch (allocation-free rule: __device__ globals) — identical set to R1
__device__ float g_q[Bb * Hh * Nn * HDd];     // [B,H,N,HD]
__device__ float g_k[Bb * Hh * Nn * HDd];
__device__ float g_v[Bb * Hh * Nn * HDd];
__device__ float g_ctx[Bb * Nn * Dout];       // [B,N,D] row-major

// ---------------------------------------------------------------------------
// 128x128x8 SGEMM body, 256 threads, 8x8 microtile per thread. (R1 verbatim —
// measured at ~96% of the FFMA-3reg issue ceiling; do not touch.)
// ---------------------------------------------------------------------------
__global__ __launch_bounds__(256) void qkv_kernel(
    const float* __restrict__ x,
    const float* __restrict__ Wq,
    const float* __restrict__ Wk,
    const float* __restrict__ Wv)
{
    __shared__ float As[8][128];
    __shared__ float Bs[8][128];

    const float* W   = (blockIdx.z == 0) ? Wq : (blockIdx.z == 1) ? Wk : Wv;
    float*       out = (blockIdx.z == 0) ? g_q : (blockIdx.z == 1) ? g_k : g_v;

    const int tid  = threadIdx.x;
    const int row0 = blockIdx.y * 128;
    const int col0 = blockIdx.x * 128;

    const int ar = tid >> 1;
    const int ac = (tid & 1) * 4;
    const int br = tid >> 5;
    const int bc = (tid & 31) * 4;
    const int ty = tid >> 4;
    const int tx = tid & 15;

    float acc[8][8];
#pragma unroll
    for (int i = 0; i < 8; i++)
#pragma unroll
        for (int j = 0; j < 8; j++) acc[i][j] = 0.f;

    for (int k0 = 0; k0 < Din; k0 += 8) {
        float4 av = *(const float4*)&x[(row0 + ar) * Din + k0 + ac];
        As[ac + 0][ar] = av.x;
        As[ac + 1][ar] = av.y;
        As[ac + 2][ar] = av.z;
        As[ac + 3][ar] = av.w;
        *(float4*)&Bs[br][bc] = *(const float4*)&W[(k0 + br) * Dout + col0 + bc];
        __syncthreads();

#pragma unroll
        for (int k = 0; k < 8; k++) {
            float4 a0 = *(float4*)&As[k][ty * 8];
            float4 a1 = *(float4*)&As[k][ty * 8 + 4];
            float4 b0 = *(float4*)&Bs[k][tx * 8];
            float4 b1 = *(float4*)&Bs[k][tx * 8 + 4];
            float a[8] = {a0.x, a0.y, a0.z, a0.w, a1.x, a1.y, a1.z, a1.w};
            float b[8] = {b0.x, b0.y, b0.z, b0.w, b1.x, b1.y, b1.z, b1.w};
#pragma unroll
            for (int i = 0; i < 8; i++)
#pragma unroll
                for (int j = 0; j < 8; j++) acc[i][j] = fmaf(a[i], b[j], acc[i][j]);
        }
        __syncthreads();
    }

#pragma unroll
    for (int i = 0; i < 8; i++) {
        int gm = row0 + ty * 8 + i;
        int b  = gm >> 11;
        int n  = gm & 2047;
#pragma unroll
        for (int j = 0; j < 8; j++) {
            int col = col0 + tx * 8 + j;
            int h   = col >> 6;
            int hd  = col & 63;
            out[((b * Hh + h) * Nn + n) * HDd + hd] = acc[i][j];
        }
    }
}

__global__ __launch_bounds__(256) void out_proj_kernel(
    const float* __restrict__ Wo,
    const float* __restrict__ bo,
    float* __restrict__ out)
{
    __shared__ float As[8][128];
    __shared__ float Bs[8][128];

    const int tid  = threadIdx.x;
    const int row0 = blockIdx.y * 128;
    const int col0 = blockIdx.x * 128;

    const int ar = tid >> 1;
    const int ac = (tid & 1) * 4;
    const int br = tid >> 5;
    const int bc = (tid & 31) * 4;
    const int ty = tid >> 4;
    const int tx = tid & 15;

    float acc[8][8];
#pragma unroll
    for (int i = 0; i < 8; i++)
#pragma unroll
        for (int j = 0; j < 8; j++) acc[i][j] = 0.f;

    for (int k0 = 0; k0 < Dout; k0 += 8) {
        float4 av = *(const float4*)&g_ctx[(row0 + ar) * Dout + k0 + ac];
        As[ac + 0][ar] = av.x;
        As[ac + 1][ar] = av.y;
        As[ac + 2][ar] = av.z;
        As[ac + 3][ar] = av.w;
        *(float4*)&Bs[br][bc] = *(const float4*)&Wo[(k0 + br) * Dout + col0 + bc];
        __syncthreads();

#pragma unroll
        for (int k = 0; k < 8; k++) {
            float4 a0 = *(float4*)&As[k][ty * 8];
            float4 a1 = *(float4*)&As[k][ty * 8 + 4];
            float4 b0 = *(float4*)&Bs[k][tx * 8];
            float4 b1 = *(float4*)&Bs[k][tx * 8 + 4];
            float a[8] = {a0.x, a0.y, a0.z, a0.w, a1.x, a1.y, a1.z, a1.w};
            float b[8] = {b0.x, b0.y, b0.z, b0.w, b1.x, b1.y, b1.z, b1.w};
#pragma unroll
            for (int i = 0; i < 8; i++)
#pragma unroll
                for (int j = 0; j < 8; j++) acc[i][j] = fmaf(a[i], b[j], acc[i][j]);
        }
        __syncthreads();
    }

#pragma unroll
    for (int i = 0; i < 8; i++) {
        int gm = row0 + ty * 8 + i;
#pragma unroll
        for (int j = 0; j < 8; j++) {
            int col = col0 + tx * 8 + j;
            out[gm * Dout + col] = acc[i][j] + bo[col];
        }
    }
}

// ---------------------------------------------------------------------------
// Flash attention (fp32, causal). BQ=128 q-rows per CTA, BK=64.
// 256 threads, microtile 8(rows) x 4(cols). Register softmax via half-warp
// shuffles (16 lanes share a row-group). Longest blocks launch first.
// smem (floats): Qst[64k][132r] @0, Kst[64k][68c] @8448, Vs[64][64] @12800,
//                Ss[128r][68j] @16896   (total 25600 floats = 100 KB)
// ---------------------------------------------------------------------------
#define FLASH_SMEM_FLOATS 25600
#define FLASH_SMEM_BYTES  (FLASH_SMEM_FLOATS * 4)

__global__ __launch_bounds__(256) void flash_kernel()
{
    extern __shared__ float sm[];
    float* Qst = sm;            // [k][r] stride 132
    float* Kst = sm + 8448;     // [k][c] stride 68
    float* Vs  = sm + 12800;    // [j][c] 64x64
    float* Ss  = sm + 16896;    // [r][j] stride 68

    const int tid = threadIdx.x;
    const int qb  = (int)gridDim.x - 1 - (int)blockIdx.x;   // longest first
    const int h   = blockIdx.y;
    const int b   = blockIdx.z;

    const float* Qp = g_q + (size_t)((b * Hh + h) * Nn + qb * 128) * HDd;
    const float* Kp = g_k + (size_t)(b * Hh + h) * Nn * HDd;
    const float* Vp = g_v + (size_t)(b * Hh + h) * Nn * HDd;

    const int lr = tid >> 4;         // 0..15
    const int lc = (tid & 15) * 4;   // 0..60
    const float sm_scale = 0.125f;   // 1/sqrt(64)

    // Load Q (128 rows, transposed, pre-scaled)
#pragma unroll
    for (int rep = 0; rep < 8; rep++) {
        int r = lr + rep * 16;
        float4 v = *(const float4*)&Qp[r * HDd + lc];
        Qst[(lc + 0) * 132 + r] = v.x * sm_scale;
        Qst[(lc + 1) * 132 + r] = v.y * sm_scale;
        Qst[(lc + 2) * 132 + r] = v.z * sm_scale;
        Qst[(lc + 3) * 132 + r] = v.w * sm_scale;
    }

    const int ty = tid >> 4;
    const int tx = tid & 15;
    const int r0 = ty * 8;           // 8 rows per thread
    const int c0 = tx * 4;

    float m_loc[8], l_loc[8];
#pragma unroll
    for (int i = 0; i < 8; i++) { m_loc[i] = -INFINITY; l_loc[i] = 0.f; }

    float acc[8][4];
#pragma unroll
    for (int i = 0; i < 8; i++)
#pragma unroll
        for (int j = 0; j < 4; j++) acc[i][j] = 0.f;

    __syncthreads();

    const int kb_max = 2 * qb + 1;
    for (int kb = 0; kb <= kb_max; kb++) {
        // Load K (transposed) and V (natural)
#pragma unroll
        for (int rep = 0; rep < 4; rep++) {
            int r = lr + rep * 16;
            float4 kv = *(const float4*)&Kp[(kb * 64 + r) * HDd + lc];
            Kst[(lc + 0) * 68 + r] = kv.x;
            Kst[(lc + 1) * 68 + r] = kv.y;
            Kst[(lc + 2) * 68 + r] = kv.z;
            Kst[(lc + 3) * 68 + r] = kv.w;
            *(float4*)&Vs[r * 64 + lc] = *(const float4*)&Vp[(kb * 64 + r) * HDd + lc];
        }
        __syncthreads();

        // S = Q K^T (8x4 per thread)
        float sacc[8][4];
#pragma unroll
        for (int i = 0; i < 8; i++)
#pragma unroll
            for (int j = 0; j < 4; j++) sacc[i][j] = 0.f;

#pragma unroll 4
        for (int k = 0; k < 64; k++) {
            float4 a0 = *(float4*)&Qst[k * 132 + r0];
            float4 a1 = *(float4*)&Qst[k * 132 + r0 + 4];
            float4 bb = *(float4*)&Kst[k * 68 + c0];
            float av[8] = {a0.x, a0.y, a0.z, a0.w, a1.x, a1.y, a1.z, a1.w};
            float bv[4] = {bb.x, bb.y, bb.z, bb.w};
#pragma unroll
            for (int i = 0; i < 8; i++)
#pragma unroll
                for (int j = 0; j < 4; j++) sacc[i][j] = fmaf(av[i], bv[j], sacc[i][j]);
        }

        // Causal mask (only the last two kv-blocks intersect the diagonal)
        if (kb >= 2 * qb) {
            const int colbase = kb * 64 + c0;
            const int rowbase = qb * 128 + r0;
#pragma unroll
            for (int i = 0; i < 8; i++)
#pragma unroll
                for (int j = 0; j < 4; j++)
                    if (colbase + j > rowbase + i) sacc[i][j] = -1e30f;
        }

        // Register softmax: per row, shuffle-reduce max & sum over 16 lanes
#pragma unroll
        for (int i = 0; i < 8; i++) {
            float rm = fmaxf(fmaxf(sacc[i][0], sacc[i][1]),
                             fmaxf(sacc[i][2], sacc[i][3]));
            rm = fmaxf(rm, __shfl_xor_sync(0xffffffffu, rm, 1));
            rm = fmaxf(rm, __shfl_xor_sync(0xffffffffu, rm, 2));
            rm = fmaxf(rm, __shfl_xor_sync(0xffffffffu, rm, 4));
            rm = fmaxf(rm, __shfl_xor_sync(0xffffffffu, rm, 8));

            float mnew = fmaxf(m_loc[i], rm);
            float scr  = __expf(m_loc[i] - mnew);
            m_loc[i] = mnew;

            float p0 = __expf(sacc[i][0] - mnew);
            float p1 = __expf(sacc[i][1] - mnew);
            float p2 = __expf(sacc[i][2] - mnew);
            float p3 = __expf(sacc[i][3] - mnew);
            float4 pv; pv.x = p0; pv.y = p1; pv.z = p2; pv.w = p3;
            *(float4*)&Ss[(r0 + i) * 68 + c0] = pv;

            float ps = (p0 + p1) + (p2 + p3);
            ps += __shfl_xor_sync(0xffffffffu, ps, 1);
            ps += __shfl_xor_sync(0xffffffffu, ps, 2);
            ps += __shfl_xor_sync(0xffffffffu, ps, 4);
            ps += __shfl_xor_sync(0xffffffffu, ps, 8);
            l_loc[i] = l_loc[i] * scr + ps;

#pragma unroll
            for (int j = 0; j < 4; j++) acc[i][j] *= scr;
        }
        __syncwarp();   // P row-group ty is written & read by the same warp

        // O += P @ V (float4 P loads, stride 68)
#pragma unroll 2
        for (int j4 = 0; j4 < 64; j4 += 4) {
            float4 v0 = *(float4*)&Vs[(j4 + 0) * 64 + c0];
            float4 v1 = *(float4*)&Vs[(j4 + 1) * 64 + c0];
            float4 v2 = *(float4*)&Vs[(j4 + 2) * 64 + c0];
            float4 v3 = *(float4*)&Vs[(j4 + 3) * 64 + c0];
#pragma unroll
            for (int i = 0; i < 8; i++) {
                float4 p = *(float4*)&Ss[(r0 + i) * 68 + j4];
                acc[i][0] = fmaf(p.x, v0.x, acc[i][0]);
                acc[i][1] = fmaf(p.x, v0.y, acc[i][1]);
                acc[i][2] = fmaf(p.x, v0.z, acc[i][2]);
                acc[i][3] = fmaf(p.x, v0.w, acc[i][3]);
                acc[i][0] = fmaf(p.y, v1.x, acc[i][0]);
                acc[i][1] = fmaf(p.y, v1.y, acc[i][1]);
                acc[i][2] = fmaf(p.y, v1.z, acc[i][2]);
                acc[i][3] = fmaf(p.y, v1.w, acc[i][3]);
                acc[i][0] = fmaf(p.z, v2.x, acc[i][0]);
                acc[i][1] = fmaf(p.z, v2.y, acc[i][1]);
                acc[i][2] = fmaf(p.z, v2.z, acc[i][2]);
                acc[i][3] = fmaf(p.z, v2.w, acc[i][3]);
                acc[i][0] = fmaf(p.w, v3.x, acc[i][0]);
                acc[i][1] = fmaf(p.w, v3.y, acc[i][1]);
                acc[i][2] = fmaf(p.w, v3.z, acc[i][2]);
                acc[i][3] = fmaf(p.w, v3.w, acc[i][3]);
            }
        }
        __syncthreads();
    }

    // Normalize and write ctx in [B,N,D]
#pragma unroll
    for (int i = 0; i < 8; i++) {
        float inv = 1.f / l_loc[i];
        int n = qb * 128 + r0 + i;
        float4 o;
        o.x = acc[i][0] * inv;
        o.y = acc[i][1] * inv;
        o.z = acc[i][2] * inv;
        o.w = acc[i][3] * inv;
        *(float4*)&g_ctx[(size_t)(b * Nn + n) * Dout + h * 64 + c0] = o;
    }
}

// ---------------------------------------------------------------------------
extern "C" void kernel_launch(void* const* d_in, const int* in_sizes, int n_in,
                              void* d_out, int out_size)
{
    const float* x  = (const float*)d_in[0];
    const float* Wq = (const float*)d_in[1];
    const float* Wk = (const float*)d_in[2];
    const float* Wv = (const float*)d_in[3];
    const float* Wo = (const float*)d_in[4];
    const float* bo = (const float*)d_in[5];
    float* out = (float*)d_out;

    cudaFuncSetAttribute(flash_kernel, cudaFuncAttributeMaxDynamicSharedMemorySize,
                         FLASH_SMEM_BYTES);

    dim3 gemm_grid(Dout / 128, (Bb * Nn) / 128, 3);
    qkv_kernel<<<gemm_grid, 256>>>(x, Wq, Wk, Wv);

    dim3 flash_grid(Nn / 128, Hh, Bb);
    flash_kernel<<<flash_grid, 256, FLASH_SMEM_BYTES>>>();

    dim3 out_grid(Dout / 128, (Bb * Nn) / 128);
    out_proj_kernel<<<out_grid, 256>>>(Wo, bo, out);
}

// round 15
// speedup vs baseline: 1.0747x; 1.0747x over previous
#include <cuda_runtime.h>
#include <math.h>

// Problem constants
#define Bb   2
#define Nn   2048
#define Din  1024
#define Dout 1024
#define Hh   16
#define HDd  64

// Scratch (allocation-free rule: __device__ globals) — identical set to R1
__device__ float g_q[Bb * Hh * Nn * HDd];     // [B,H,N,HD]
__device__ float g_k[Bb * Hh * Nn * HDd];
__device__ float g_v[Bb * Hh * Nn * HDd];
__device__ float g_ctx[Bb * Nn * Dout];       // [B,N,D] row-major

// ---------------------------------------------------------------------------
// 128x128x8 SGEMM, 256 threads, 8x8 microtile + register prefetch of the
// next K-chunk (hides LDG latency behind the 512-FMA compute phase).
// ---------------------------------------------------------------------------
__global__ __launch_bounds__(256) void qkv_kernel(
    const float* __restrict__ x,
    const float* __restrict__ Wq,
    const float* __restrict__ Wk,
    const float* __restrict__ Wv)
{
    __shared__ float As[8][128];
    __shared__ float Bs[8][128];

    const float* W   = (blockIdx.z == 0) ? Wq : (blockIdx.z == 1) ? Wk : Wv;
    float*       out = (blockIdx.z == 0) ? g_q : (blockIdx.z == 1) ? g_k : g_v;

    const int tid  = threadIdx.x;
    const int row0 = blockIdx.y * 128;
    const int col0 = blockIdx.x * 128;

    const int ar = tid >> 1;
    const int ac = (tid & 1) * 4;
    const int br = tid >> 5;
    const int bc = (tid & 31) * 4;
    const int ty = tid >> 4;
    const int tx = tid & 15;

    float acc[8][8];
#pragma unroll
    for (int i = 0; i < 8; i++)
#pragma unroll
        for (int j = 0; j < 8; j++) acc[i][j] = 0.f;

    // Prologue: prefetch chunk 0
    float4 avr = *(const float4*)&x[(row0 + ar) * Din + ac];
    float4 bvr = *(const float4*)&W[br * Dout + col0 + bc];

    for (int k0 = 0; k0 < Din; k0 += 8) {
        As[ac + 0][ar] = avr.x;
        As[ac + 1][ar] = avr.y;
        As[ac + 2][ar] = avr.z;
        As[ac + 3][ar] = avr.w;
        *(float4*)&Bs[br][bc] = bvr;
        __syncthreads();

        if (k0 + 8 < Din) {
            avr = *(const float4*)&x[(row0 + ar) * Din + k0 + 8 + ac];
            bvr = *(const float4*)&W[(k0 + 8 + br) * Dout + col0 + bc];
        }

#pragma unroll
        for (int k = 0; k < 8; k++) {
            float4 a0 = *(float4*)&As[k][ty * 8];
            float4 a1 = *(float4*)&As[k][ty * 8 + 4];
            float4 b0 = *(float4*)&Bs[k][tx * 8];
            float4 b1 = *(float4*)&Bs[k][tx * 8 + 4];
            float a[8] = {a0.x, a0.y, a0.z, a0.w, a1.x, a1.y, a1.z, a1.w};
            float b[8] = {b0.x, b0.y, b0.z, b0.w, b1.x, b1.y, b1.z, b1.w};
#pragma unroll
            for (int i = 0; i < 8; i++)
#pragma unroll
                for (int j = 0; j < 8; j++) acc[i][j] = fmaf(a[i], b[j], acc[i][j]);
        }
        __syncthreads();
    }

#pragma unroll
    for (int i = 0; i < 8; i++) {
        int gm = row0 + ty * 8 + i;
        int b  = gm >> 11;
        int n  = gm & 2047;
#pragma unroll
        for (int j = 0; j < 8; j++) {
            int col = col0 + tx * 8 + j;
            int h   = col >> 6;
            int hd  = col & 63;
            out[((b * Hh + h) * Nn + n) * HDd + hd] = acc[i][j];
        }
    }
}

__global__ __launch_bounds__(256) void out_proj_kernel(
    const float* __restrict__ Wo,
    const float* __restrict__ bo,
    float* __restrict__ out)
{
    __shared__ float As[8][128];
    __shared__ float Bs[8][128];

    const int tid  = threadIdx.x;
    const int row0 = blockIdx.y * 128;
    const int col0 = blockIdx.x * 128;

    const int ar = tid >> 1;
    const int ac = (tid & 1) * 4;
    const int br = tid >> 5;
    const int bc = (tid & 31) * 4;
    const int ty = tid >> 4;
    const int tx = tid & 15;

    float acc[8][8];
#pragma unroll
    for (int i = 0; i < 8; i++)
#pragma unroll
        for (int j = 0; j < 8; j++) acc[i][j] = 0.f;

    float4 avr = *(const float4*)&g_ctx[(row0 + ar) * Dout + ac];
    float4 bvr = *(const float4*)&Wo[br * Dout + col0 + bc];

    for (int k0 = 0; k0 < Dout; k0 += 8) {
        As[ac + 0][ar] = avr.x;
        As[ac + 1][ar] = avr.y;
        As[ac + 2][ar] = avr.z;
        As[ac + 3][ar] = avr.w;
        *(float4*)&Bs[br][bc] = bvr;
        __syncthreads();

        if (k0 + 8 < Dout) {
            avr = *(const float4*)&g_ctx[(row0 + ar) * Dout + k0 + 8 + ac];
            bvr = *(const float4*)&Wo[(k0 + 8 + br) * Dout + col0 + bc];
        }

#pragma unroll
        for (int k = 0; k < 8; k++) {
            float4 a0 = *(float4*)&As[k][ty * 8];
            float4 a1 = *(float4*)&As[k][ty * 8 + 4];
            float4 b0 = *(float4*)&Bs[k][tx * 8];
            float4 b1 = *(float4*)&Bs[k][tx * 8 + 4];
            float a[8] = {a0.x, a0.y, a0.z, a0.w, a1.x, a1.y, a1.z, a1.w};
            float b[8] = {b0.x, b0.y, b0.z, b0.w, b1.x, b1.y, b1.z, b1.w};
#pragma unroll
            for (int i = 0; i < 8; i++)
#pragma unroll
                for (int j = 0; j < 8; j++) acc[i][j] = fmaf(a[i], b[j], acc[i][j]);
        }
        __syncthreads();
    }

#pragma unroll
    for (int i = 0; i < 8; i++) {
        int gm = row0 + ty * 8 + i;
#pragma unroll
        for (int j = 0; j < 8; j++) {
            int col = col0 + tx * 8 + j;
            out[gm * Dout + col] = acc[i][j] + bo[col];
        }
    }
}

// ---------------------------------------------------------------------------
// Flash attention (fp32, causal). R13 config (BQ=64, 3 CTAs/SM) + register
// prefetch of next K/V block. Register softmax via half-warp shuffles.
// smem (floats): Qst[64k][68] @0, Kst[64k][68] @4352, Vs[64][64] @8704,
//                Ss[64 r][68] @12800
// ---------------------------------------------------------------------------
#define FLASH_SMEM_FLOATS 17152
#define FLASH_SMEM_BYTES  (FLASH_SMEM_FLOATS * 4)

__global__ __launch_bounds__(256) void flash_kernel()
{
    extern __shared__ float sm[];
    float* Qst = sm;            // [k][r] stride 68
    float* Kst = sm + 4352;     // [k][c] stride 68
    float* Vs  = sm + 8704;     // [j][c] 64x64
    float* Ss  = sm + 12800;    // [r][j] stride 68

    const int tid = threadIdx.x;
    const int qb  = (int)gridDim.x - 1 - (int)blockIdx.x;   // longest first
    const int h   = blockIdx.y;
    const int b   = blockIdx.z;

    const float* Qp = g_q + (size_t)((b * Hh + h) * Nn + qb * 64) * HDd;
    const float* Kp = g_k + (size_t)(b * Hh + h) * Nn * HDd;
    const float* Vp = g_v + (size_t)(b * Hh + h) * Nn * HDd;

    const int lr = tid >> 4;         // 0..15
    const int lc = (tid & 15) * 4;   // 0..60
    const float sm_scale = 0.125f;   // 1/sqrt(64)

    // Load Q (transposed, pre-scaled). Covered by the loop-top barrier.
#pragma unroll
    for (int rep = 0; rep < 4; rep++) {
        int r = lr + rep * 16;
        float4 v = *(const float4*)&Qp[r * HDd + lc];
        Qst[(lc + 0) * 68 + r] = v.x * sm_scale;
        Qst[(lc + 1) * 68 + r] = v.y * sm_scale;
        Qst[(lc + 2) * 68 + r] = v.z * sm_scale;
        Qst[(lc + 3) * 68 + r] = v.w * sm_scale;
    }

    const int ty = tid >> 4;
    const int tx = tid & 15;
    const int r0 = ty * 4;
    const int c0 = tx * 4;

    float m_loc[4], l_loc[4];
#pragma unroll
    for (int i = 0; i < 4; i++) { m_loc[i] = -INFINITY; l_loc[i] = 0.f; }

    float acc[4][4];
#pragma unroll
    for (int i = 0; i < 4; i++)
#pragma unroll
        for (int j = 0; j < 4; j++) acc[i][j] = 0.f;

    // Prologue: prefetch K/V block 0 into registers
    float4 kr0 = *(const float4*)&Kp[(lr     ) * HDd + lc];
    float4 kr1 = *(const float4*)&Kp[(lr + 16) * HDd + lc];
    float4 kr2 = *(const float4*)&Kp[(lr + 32) * HDd + lc];
    float4 kr3 = *(const float4*)&Kp[(lr + 48) * HDd + lc];
    float4 vv0 = *(const float4*)&Vp[(lr     ) * HDd + lc];
    float4 vv1 = *(const float4*)&Vp[(lr + 16) * HDd + lc];
    float4 vv2 = *(const float4*)&Vp[(lr + 32) * HDd + lc];
    float4 vv3 = *(const float4*)&Vp[(lr + 48) * HDd + lc];

    for (int kb = 0; kb <= qb; kb++) {
        // Store prefetched K (transposed) and V (natural)
        Kst[(lc + 0) * 68 + lr     ] = kr0.x;
        Kst[(lc + 1) * 68 + lr     ] = kr0.y;
        Kst[(lc + 2) * 68 + lr     ] = kr0.z;
        Kst[(lc + 3) * 68 + lr     ] = kr0.w;
        Kst[(lc + 0) * 68 + lr + 16] = kr1.x;
        Kst[(lc + 1) * 68 + lr + 16] = kr1.y;
        Kst[(lc + 2) * 68 + lr + 16] = kr1.z;
        Kst[(lc + 3) * 68 + lr + 16] = kr1.w;
        Kst[(lc + 0) * 68 + lr + 32] = kr2.x;
        Kst[(lc + 1) * 68 + lr + 32] = kr2.y;
        Kst[(lc + 2) * 68 + lr + 32] = kr2.z;
        Kst[(lc + 3) * 68 + lr + 32] = kr2.w;
        Kst[(lc + 0) * 68 + lr + 48] = kr3.x;
        Kst[(lc + 1) * 68 + lr + 48] = kr3.y;
        Kst[(lc + 2) * 68 + lr + 48] = kr3.z;
        Kst[(lc + 3) * 68 + lr + 48] = kr3.w;
        *(float4*)&Vs[(lr     ) * 64 + lc] = vv0;
        *(float4*)&Vs[(lr + 16) * 64 + lc] = vv1;
        *(float4*)&Vs[(lr + 32) * 64 + lc] = vv2;
        *(float4*)&Vs[(lr + 48) * 64 + lc] = vv3;
        __syncthreads();

        // Prefetch next K/V block (latency hidden under QK^T + PV compute)
        if (kb + 1 <= qb) {
            const float* kp = Kp + (size_t)(kb + 1) * 64 * HDd;
            const float* vp = Vp + (size_t)(kb + 1) * 64 * HDd;
            kr0 = *(const float4*)&kp[(lr     ) * HDd + lc];
            kr1 = *(const float4*)&kp[(lr + 16) * HDd + lc];
            kr2 = *(const float4*)&kp[(lr + 32) * HDd + lc];
            kr3 = *(const float4*)&kp[(lr + 48) * HDd + lc];
            vv0 = *(const float4*)&vp[(lr     ) * HDd + lc];
            vv1 = *(const float4*)&vp[(lr + 16) * HDd + lc];
            vv2 = *(const float4*)&vp[(lr + 32) * HDd + lc];
            vv3 = *(const float4*)&vp[(lr + 48) * HDd + lc];
        }

        // S = Q K^T (4x4 per thread)
        float sacc[4][4];
#pragma unroll
        for (int i = 0; i < 4; i++)
#pragma unroll
            for (int j = 0; j < 4; j++) sacc[i][j] = 0.f;

#pragma unroll 8
        for (int k = 0; k < 64; k++) {
            float4 a = *(float4*)&Qst[k * 68 + r0];
            float4 bb = *(float4*)&Kst[k * 68 + c0];
            float av[4] = {a.x, a.y, a.z, a.w};
            float bv[4] = {bb.x, bb.y, bb.z, bb.w};
#pragma unroll
            for (int i = 0; i < 4; i++)
#pragma unroll
                for (int j = 0; j < 4; j++) sacc[i][j] = fmaf(av[i], bv[j], sacc[i][j]);
        }

        // Causal mask on the diagonal block (in registers)
        if (kb == qb) {
#pragma unroll
            for (int i = 0; i < 4; i++)
#pragma unroll
                for (int j = 0; j < 4; j++)
                    if (c0 + j > r0 + i) sacc[i][j] = -1e30f;
        }

        // Register softmax: per row, shuffle-reduce max & sum over 16 lanes
#pragma unroll
        for (int i = 0; i < 4; i++) {
            float rm = fmaxf(fmaxf(sacc[i][0], sacc[i][1]),
                             fmaxf(sacc[i][2], sacc[i][3]));
            rm = fmaxf(rm, __shfl_xor_sync(0xffffffffu, rm, 1));
            rm = fmaxf(rm, __shfl_xor_sync(0xffffffffu, rm, 2));
            rm = fmaxf(rm, __shfl_xor_sync(0xffffffffu, rm, 4));
            rm = fmaxf(rm, __shfl_xor_sync(0xffffffffu, rm, 8));

            float mnew = fmaxf(m_loc[i], rm);
            float scr  = __expf(m_loc[i] - mnew);
            m_loc[i] = mnew;

            float p0 = __expf(sacc[i][0] - mnew);
            float p1 = __expf(sacc[i][1] - mnew);
            float p2 = __expf(sacc[i][2] - mnew);
            float p3 = __expf(sacc[i][3] - mnew);
            float4 pv; pv.x = p0; pv.y = p1; pv.z = p2; pv.w = p3;
            *(float4*)&Ss[(r0 + i) * 68 + c0] = pv;

            float ps = (p0 + p1) + (p2 + p3);
            ps += __shfl_xor_sync(0xffffffffu, ps, 1);
            ps += __shfl_xor_sync(0xffffffffu, ps, 2);
            ps += __shfl_xor_sync(0xffffffffu, ps, 4);
            ps += __shfl_xor_sync(0xffffffffu, ps, 8);
            l_loc[i] = l_loc[i] * scr + ps;

#pragma unroll
            for (int j = 0; j < 4; j++) acc[i][j] *= scr;
        }
        __syncwarp();   // P rows for group ty are written & read by the same warp

        // O += P @ V (float4 P loads, stride 68)
#pragma unroll 4
        for (int j4 = 0; j4 < 64; j4 += 4) {
            float4 v0 = *(float4*)&Vs[(j4 + 0) * 64 + c0];
            float4 v1 = *(float4*)&Vs[(j4 + 1) * 64 + c0];
            float4 v2 = *(float4*)&Vs[(j4 + 2) * 64 + c0];
            float4 v3 = *(float4*)&Vs[(j4 + 3) * 64 + c0];
#pragma unroll
            for (int i = 0; i < 4; i++) {
                float4 p = *(float4*)&Ss[(r0 + i) * 68 + j4];
                acc[i][0] = fmaf(p.x, v0.x, acc[i][0]);
                acc[i][1] = fmaf(p.x, v0.y, acc[i][1]);
                acc[i][2] = fmaf(p.x, v0.z, acc[i][2]);
                acc[i][3] = fmaf(p.x, v0.w, acc[i][3]);
                acc[i][0] = fmaf(p.y, v1.x, acc[i][0]);
                acc[i][1] = fmaf(p.y, v1.y, acc[i][1]);
                acc[i][2] = fmaf(p.y, v1.z, acc[i][2]);
                acc[i][3] = fmaf(p.y, v1.w, acc[i][3]);
                acc[i][0] = fmaf(p.z, v2.x, acc[i][0]);
                acc[i][1] = fmaf(p.z, v2.y, acc[i][1]);
                acc[i][2] = fmaf(p.z, v2.z, acc[i][2]);
                acc[i][3] = fmaf(p.z, v2.w, acc[i][3]);
                acc[i][0] = fmaf(p.w, v3.x, acc[i][0]);
                acc[i][1] = fmaf(p.w, v3.y, acc[i][1]);
                acc[i][2] = fmaf(p.w, v3.z, acc[i][2]);
                acc[i][3] = fmaf(p.w, v3.w, acc[i][3]);
            }
        }
        __syncthreads();
    }

    // Normalize and write ctx in [B,N,D]
#pragma unroll
    for (int i = 0; i < 4; i++) {
        float inv = 1.f / l_loc[i];
        int n = qb * 64 + r0 + i;
        float4 o;
        o.x = acc[i][0] * inv;
        o.y = acc[i][1] * inv;
        o.z = acc[i][2] * inv;
        o.w = acc[i][3] * inv;
        *(float4*)&g_ctx[(size_t)(b * Nn + n) * Dout + h * 64 + c0] = o;
    }
}

// ---------------------------------------------------------------------------
extern "C" void kernel_launch(void* const* d_in, const int* in_sizes, int n_in,
                              void* d_out, int out_size)
{
    const float* x  = (const float*)d_in[0];
    const float* Wq = (const float*)d_in[1];
    const float* Wk = (const float*)d_in[2];
    const float* Wv = (const float*)d_in[3];
    const float* Wo = (const float*)d_in[4];
    const float* bo = (const float*)d_in[5];
    float* out = (float*)d_out;

    cudaFuncSetAttribute(flash_kernel, cudaFuncAttributeMaxDynamicSharedMemorySize,
                         FLASH_SMEM_BYTES);

    dim3 gemm_grid(Dout / 128, (Bb * Nn) / 128, 3);
    qkv_kernel<<<gemm_grid, 256>>>(x, Wq, Wk, Wv);

    dim3 flash_grid(Nn / 64, Hh, Bb);
    flash_kernel<<<flash_grid, 256, FLASH_SMEM_BYTES>>>();

    dim3 out_grid(Dout / 128, (Bb * Nn) / 128);
    out_proj_kernel<<<out_grid, 256>>>(Wo, bo, out);
}

// round 16
// speedup vs baseline: 1.0816x; 1.0064x over previous
#include <cuda_runtime.h>
#include <math.h>

// Problem constants
#define Bb   2
#define Nn   2048
#define Din  1024
#define Dout 1024
#define Hh   16
#define HDd  64

// Scratch (allocation-free rule: __device__ globals) — identical set to R1
__device__ float g_q[Bb * Hh * Nn * HDd];     // [B,H,N,HD]
__device__ float g_k[Bb * Hh * Nn * HDd];
__device__ float g_v[Bb * Hh * Nn * HDd];
__device__ float g_ctx[Bb * Nn * Dout];       // [B,N,D] row-major

// ---------------------------------------------------------------------------
// 128x128x8 SGEMM, 256 threads, 8x8 microtile + register prefetch of the
// next K-chunk (hides LDG latency behind the 512-FMA compute phase).
// ---------------------------------------------------------------------------
__global__ __launch_bounds__(256) void qkv_kernel(
    const float* __restrict__ x,
    const float* __restrict__ Wq,
    const float* __restrict__ Wk,
    const float* __restrict__ Wv)
{
    __shared__ float As[8][128];
    __shared__ float Bs[8][128];

    const float* W   = (blockIdx.z == 0) ? Wq : (blockIdx.z == 1) ? Wk : Wv;
    float*       out = (blockIdx.z == 0) ? g_q : (blockIdx.z == 1) ? g_k : g_v;

    const int tid  = threadIdx.x;
    const int row0 = blockIdx.y * 128;
    const int col0 = blockIdx.x * 128;

    const int ar = tid >> 1;
    const int ac = (tid & 1) * 4;
    const int br = tid >> 5;
    const int bc = (tid & 31) * 4;
    const int ty = tid >> 4;
    const int tx = tid & 15;

    float acc[8][8];
#pragma unroll
    for (int i = 0; i < 8; i++)
#pragma unroll
        for (int j = 0; j < 8; j++) acc[i][j] = 0.f;

    // Prologue: prefetch chunk 0
    float4 avr = *(const float4*)&x[(row0 + ar) * Din + ac];
    float4 bvr = *(const float4*)&W[br * Dout + col0 + bc];

    for (int k0 = 0; k0 < Din; k0 += 8) {
        As[ac + 0][ar] = avr.x;
        As[ac + 1][ar] = avr.y;
        As[ac + 2][ar] = avr.z;
        As[ac + 3][ar] = avr.w;
        *(float4*)&Bs[br][bc] = bvr;
        __syncthreads();

        if (k0 + 8 < Din) {
            avr = *(const float4*)&x[(row0 + ar) * Din + k0 + 8 + ac];
            bvr = *(const float4*)&W[(k0 + 8 + br) * Dout + col0 + bc];
        }

#pragma unroll
        for (int k = 0; k < 8; k++) {
            float4 a0 = *(float4*)&As[k][ty * 8];
            float4 a1 = *(float4*)&As[k][ty * 8 + 4];
            float4 b0 = *(float4*)&Bs[k][tx * 8];
            float4 b1 = *(float4*)&Bs[k][tx * 8 + 4];
            float a[8] = {a0.x, a0.y, a0.z, a0.w, a1.x, a1.y, a1.z, a1.w};
            float b[8] = {b0.x, b0.y, b0.z, b0.w, b1.x, b1.y, b1.z, b1.w};
#pragma unroll
            for (int i = 0; i < 8; i++)
#pragma unroll
                for (int j = 0; j < 8; j++) acc[i][j] = fmaf(a[i], b[j], acc[i][j]);
        }
        __syncthreads();
    }

#pragma unroll
    for (int i = 0; i < 8; i++) {
        int gm = row0 + ty * 8 + i;
        int b  = gm >> 11;
        int n  = gm & 2047;
#pragma unroll
        for (int j = 0; j < 8; j++) {
            int col = col0 + tx * 8 + j;
            int h   = col >> 6;
            int hd  = col & 63;
            out[((b * Hh + h) * Nn + n) * HDd + hd] = acc[i][j];
        }
    }
}

__global__ __launch_bounds__(256) void out_proj_kernel(
    const float* __restrict__ Wo,
    const float* __restrict__ bo,
    float* __restrict__ out)
{
    __shared__ float As[8][128];
    __shared__ float Bs[8][128];

    const int tid  = threadIdx.x;
    const int row0 = blockIdx.y * 128;
    const int col0 = blockIdx.x * 128;

    const int ar = tid >> 1;
    const int ac = (tid & 1) * 4;
    const int br = tid >> 5;
    const int bc = (tid & 31) * 4;
    const int ty = tid >> 4;
    const int tx = tid & 15;

    float acc[8][8];
#pragma unroll
    for (int i = 0; i < 8; i++)
#pragma unroll
        for (int j = 0; j < 8; j++) acc[i][j] = 0.f;

    float4 avr = *(const float4*)&g_ctx[(row0 + ar) * Dout + ac];
    float4 bvr = *(const float4*)&Wo[br * Dout + col0 + bc];

    for (int k0 = 0; k0 < Dout; k0 += 8) {
        As[ac + 0][ar] = avr.x;
        As[ac + 1][ar] = avr.y;
        As[ac + 2][ar] = avr.z;
        As[ac + 3][ar] = avr.w;
        *(float4*)&Bs[br][bc] = bvr;
        __syncthreads();

        if (k0 + 8 < Dout) {
            avr = *(const float4*)&g_ctx[(row0 + ar) * Dout + k0 + 8 + ac];
            bvr = *(const float4*)&Wo[(k0 + 8 + br) * Dout + col0 + bc];
        }

#pragma unroll
        for (int k = 0; k < 8; k++) {
            float4 a0 = *(float4*)&As[k][ty * 8];
            float4 a1 = *(float4*)&As[k][ty * 8 + 4];
            float4 b0 = *(float4*)&Bs[k][tx * 8];
            float4 b1 = *(float4*)&Bs[k][tx * 8 + 4];
            float a[8] = {a0.x, a0.y, a0.z, a0.w, a1.x, a1.y, a1.z, a1.w};
            float b[8] = {b0.x, b0.y, b0.z, b0.w, b1.x, b1.y, b1.z, b1.w};
#pragma unroll
            for (int i = 0; i < 8; i++)
#pragma unroll
                for (int j = 0; j < 8; j++) acc[i][j] = fmaf(a[i], b[j], acc[i][j]);
        }
        __syncthreads();
    }

#pragma unroll
    for (int i = 0; i < 8; i++) {
        int gm = row0 + ty * 8 + i;
#pragma unroll
        for (int j = 0; j < 8; j++) {
            int col = col0 + tx * 8 + j;
            out[gm * Dout + col] = acc[i][j] + bo[col];
        }
    }
}

// ---------------------------------------------------------------------------
// Flash attention (fp32, causal). R13 config (BQ=64, 3 CTAs/SM) + register
// prefetch of next K/V block. Register softmax via half-warp shuffles.
// smem (floats): Qst[64k][68] @0, Kst[64k][68] @4352, Vs[64][64] @8704,
//                Ss[64 r][68] @12800
// ---------------------------------------------------------------------------
#define FLASH_SMEM_FLOATS 17152
#define FLASH_SMEM_BYTES  (FLASH_SMEM_FLOATS * 4)

__global__ __launch_bounds__(256) void flash_kernel()
{
    extern __shared__ float sm[];
    float* Qst = sm;            // [k][r] stride 68
    float* Kst = sm + 4352;     // [k][c] stride 68
    float* Vs  = sm + 8704;     // [j][c] 64x64
    float* Ss  = sm + 12800;    // [r][j] stride 68

    const int tid = threadIdx.x;
    const int qb  = (int)gridDim.x - 1 - (int)blockIdx.x;   // longest first
    const int h   = blockIdx.y;
    const int b   = blockIdx.z;

    const float* Qp = g_q + (size_t)((b * Hh + h) * Nn + qb * 64) * HDd;
    const float* Kp = g_k + (size_t)(b * Hh + h) * Nn * HDd;
    const float* Vp = g_v + (size_t)(b * Hh + h) * Nn * HDd;

    const int lr = tid >> 4;         // 0..15
    const int lc = (tid & 15) * 4;   // 0..60
    const float sm_scale = 0.125f;   // 1/sqrt(64)

    // Load Q (transposed, pre-scaled). Covered by the loop-top barrier.
#pragma unroll
    for (int rep = 0; rep < 4; rep++) {
        int r = lr + rep * 16;
        float4 v = *(const float4*)&Qp[r * HDd + lc];
        Qst[(lc + 0) * 68 + r] = v.x * sm_scale;
        Qst[(lc + 1) * 68 + r] = v.y * sm_scale;
        Qst[(lc + 2) * 68 + r] = v.z * sm_scale;
        Qst[(lc + 3) * 68 + r] = v.w * sm_scale;
    }

    const int ty = tid >> 4;
    const int tx = tid & 15;
    const int r0 = ty * 4;
    const int c0 = tx * 4;

    float m_loc[4], l_loc[4];
#pragma unroll
    for (int i = 0; i < 4; i++) { m_loc[i] = -INFINITY; l_loc[i] = 0.f; }

    float acc[4][4];
#pragma unroll
    for (int i = 0; i < 4; i++)
#pragma unroll
        for (int j = 0; j < 4; j++) acc[i][j] = 0.f;

    // Prologue: prefetch K/V block 0 into registers
    float4 kr0 = *(const float4*)&Kp[(lr     ) * HDd + lc];
    float4 kr1 = *(const float4*)&Kp[(lr + 16) * HDd + lc];
    float4 kr2 = *(const float4*)&Kp[(lr + 32) * HDd + lc];
    float4 kr3 = *(const float4*)&Kp[(lr + 48) * HDd + lc];
    float4 vv0 = *(const float4*)&Vp[(lr     ) * HDd + lc];
    float4 vv1 = *(const float4*)&Vp[(lr + 16) * HDd + lc];
    float4 vv2 = *(const float4*)&Vp[(lr + 32) * HDd + lc];
    float4 vv3 = *(const float4*)&Vp[(lr + 48) * HDd + lc];

    for (int kb = 0; kb <= qb; kb++) {
        // Store prefetched K (transposed) and V (natural)
        Kst[(lc + 0) * 68 + lr     ] = kr0.x;
        Kst[(lc + 1) * 68 + lr     ] = kr0.y;
        Kst[(lc + 2) * 68 + lr     ] = kr0.z;
        Kst[(lc + 3) * 68 + lr     ] = kr0.w;
        Kst[(lc + 0) * 68 + lr + 16] = kr1.x;
        Kst[(lc + 1) * 68 + lr + 16] = kr1.y;
        Kst[(lc + 2) * 68 + lr + 16] = kr1.z;
        Kst[(lc + 3) * 68 + lr + 16] = kr1.w;
        Kst[(lc + 0) * 68 + lr + 32] = kr2.x;
        Kst[(lc + 1) * 68 + lr + 32] = kr2.y;
        Kst[(lc + 2) * 68 + lr + 32] = kr2.z;
        Kst[(lc + 3) * 68 + lr + 32] = kr2.w;
        Kst[(lc + 0) * 68 + lr + 48] = kr3.x;
        Kst[(lc + 1) * 68 + lr + 48] = kr3.y;
        Kst[(lc + 2) * 68 + lr + 48] = kr3.z;
        Kst[(lc + 3) * 68 + lr + 48] = kr3.w;
        *(float4*)&Vs[(lr     ) * 64 + lc] = vv0;
        *(float4*)&Vs[(lr + 16) * 64 + lc] = vv1;
        *(float4*)&Vs[(lr + 32) * 64 + lc] = vv2;
        *(float4*)&Vs[(lr + 48) * 64 + lc] = vv3;
        __syncthreads();

        // Prefetch next K/V block (latency hidden under QK^T + PV compute)
        if (kb + 1 <= qb) {
            const float* kp = Kp + (size_t)(kb + 1) * 64 * HDd;
            const float* vp = Vp + (size_t)(kb + 1) * 64 * HDd;
            kr0 = *(const float4*)&kp[(lr     ) * HDd + lc];
            kr1 = *(const float4*)&kp[(lr + 16) * HDd + lc];
            kr2 = *(const float4*)&kp[(lr + 32) * HDd + lc];
            kr3 = *(const float4*)&kp[(lr + 48) * HDd + lc];
            vv0 = *(const float4*)&vp[(lr     ) * HDd + lc];
            vv1 = *(const float4*)&vp[(lr + 16) * HDd + lc];
            vv2 = *(const float4*)&vp[(lr + 32) * HDd + lc];
            vv3 = *(const float4*)&vp[(lr + 48) * HDd + lc];
        }

        // S = Q K^T (4x4 per thread)
        float sacc[4][4];
#pragma unroll
        for (int i = 0; i < 4; i++)
#pragma unroll
            for (int j = 0; j < 4; j++) sacc[i][j] = 0.f;

#pragma unroll 8
        for (int k = 0; k < 64; k++) {
            float4 a = *(float4*)&Qst[k * 68 + r0];
            float4 bb = *(float4*)&Kst[k * 68 + c0];
            float av[4] = {a.x, a.y, a.z, a.w};
            float bv[4] = {bb.x, bb.y, bb.z, bb.w};
#pragma unroll
            for (int i = 0; i < 4; i++)
#pragma unroll
                for (int j = 0; j < 4; j++) sacc[i][j] = fmaf(av[i], bv[j], sacc[i][j]);
        }

        // Causal mask on the diagonal block (in registers)
        if (kb == qb) {
#pragma unroll
            for (int i = 0; i < 4; i++)
#pragma unroll
                for (int j = 0; j < 4; j++)
                    if (c0 + j > r0 + i) sacc[i][j] = -1e30f;
        }

        // Register softmax: per row, shuffle-reduce max & sum over 16 lanes
#pragma unroll
        for (int i = 0; i < 4; i++) {
            float rm = fmaxf(fmaxf(sacc[i][0], sacc[i][1]),
                             fmaxf(sacc[i][2], sacc[i][3]));
            rm = fmaxf(rm, __shfl_xor_sync(0xffffffffu, rm, 1));
            rm = fmaxf(rm, __shfl_xor_sync(0xffffffffu, rm, 2));
            rm = fmaxf(rm, __shfl_xor_sync(0xffffffffu, rm, 4));
            rm = fmaxf(rm, __shfl_xor_sync(0xffffffffu, rm, 8));

            float mnew = fmaxf(m_loc[i], rm);
            float scr  = __expf(m_loc[i] - mnew);
            m_loc[i] = mnew;

            float p0 = __expf(sacc[i][0] - mnew);
            float p1 = __expf(sacc[i][1] - mnew);
            float p2 = __expf(sacc[i][2] - mnew);
            float p3 = __expf(sacc[i][3] - mnew);
            float4 pv; pv.x = p0; pv.y = p1; pv.z = p2; pv.w = p3;
            *(float4*)&Ss[(r0 + i) * 68 + c0] = pv;

            float ps = (p0 + p1) + (p2 + p3);
            ps += __shfl_xor_sync(0xffffffffu, ps, 1);
            ps += __shfl_xor_sync(0xffffffffu, ps, 2);
            ps += __shfl_xor_sync(0xffffffffu, ps, 4);
            ps += __shfl_xor_sync(0xffffffffu, ps, 8);
            l_loc[i] = l_loc[i] * scr + ps;

#pragma unroll
            for (int j = 0; j < 4; j++) acc[i][j] *= scr;
        }
        __syncwarp();   // P rows for group ty are written & read by the same warp

        // O += P @ V (float4 P loads, stride 68)
#pragma unroll 4
        for (int j4 = 0; j4 < 64; j4 += 4) {
            float4 v0 = *(float4*)&Vs[(j4 + 0) * 64 + c0];
            float4 v1 = *(float4*)&Vs[(j4 + 1) * 64 + c0];
            float4 v2 = *(float4*)&Vs[(j4 + 2) * 64 + c0];
            float4 v3 = *(float4*)&Vs[(j4 + 3) * 64 + c0];
#pragma unroll
            for (int i = 0; i < 4; i++) {
                float4 p = *(float4*)&Ss[(r0 + i) * 68 + j4];
                acc[i][0] = fmaf(p.x, v0.x, acc[i][0]);
                acc[i][1] = fmaf(p.x, v0.y, acc[i][1]);
                acc[i][2] = fmaf(p.x, v0.z, acc[i][2]);
                acc[i][3] = fmaf(p.x, v0.w, acc[i][3]);
                acc[i][0] = fmaf(p.y, v1.x, acc[i][0]);
                acc[i][1] = fmaf(p.y, v1.y, acc[i][1]);
                acc[i][2] = fmaf(p.y, v1.z, acc[i][2]);
                acc[i][3] = fmaf(p.y, v1.w, acc[i][3]);
                acc[i][0] = fmaf(p.z, v2.x, acc[i][0]);
                acc[i][1] = fmaf(p.z, v2.y, acc[i][1]);
                acc[i][2] = fmaf(p.z, v2.z, acc[i][2]);
                acc[i][3] = fmaf(p.z, v2.w, acc[i][3]);
                acc[i][0] = fmaf(p.w, v3.x, acc[i][0]);
                acc[i][1] = fmaf(p.w, v3.y, acc[i][1]);
                acc[i][2] = fmaf(p.w, v3.z, acc[i][2]);
                acc[i][3] = fmaf(p.w, v3.w, acc[i][3]);
            }
        }
        __syncthreads();
    }

    // Normalize and write ctx in [B,N,D]
#pragma unroll
    for (int i = 0; i < 4; i++) {
        float inv = 1.f / l_loc[i];
        int n = qb * 64 + r0 + i;
        float4 o;
        o.x = acc[i][0] * inv;
        o.y = acc[i][1] * inv;
        o.z = acc[i][2] * inv;
        o.w = acc[i][3] * inv;
        *(float4*)&g_ctx[(size_t)(b * Nn + n) * Dout + h * 64 + c0] = o;
    }
}

// ---------------------------------------------------------------------------
extern "C" void kernel_launch(void* const* d_in, const int* in_sizes, int n_in,
                              void* d_out, int out_size)
{
    const float* x  = (const float*)d_in[0];
    const float* Wq = (const float*)d_in[1];
    const float* Wk = (const float*)d_in[2];
    const float* Wv = (const float*)d_in[3];
    const float* Wo = (const float*)d_in[4];
    const float* bo = (const float*)d_in[5];
    float* out = (float*)d_out;

    cudaFuncSetAttribute(flash_kernel, cudaFuncAttributeMaxDynamicSharedMemorySize,
                         FLASH_SMEM_BYTES);

    dim3 gemm_grid(Dout / 128, (Bb * Nn) / 128, 3);
    qkv_kernel<<<gemm_grid, 256>>>(x, Wq, Wk, Wv);

    dim3 flash_grid(Nn / 64, Hh, Bb);
    flash_kernel<<<flash_grid, 256, FLASH_SMEM_BYTES>>>();

    dim3 out_grid(Dout / 128, (Bb * Nn) / 128);
    out_proj_kernel<<<out_grid, 256>>>(Wo, bo, out);
}